// round 7
// baseline (speedup 1.0000x reference)
#include <cuda_runtime.h>

#define HIDDEN 2048
#define INTER  1408
#define TOPK   6

// Scratch for intermediate activations (silu(gate)*up): 6*1408 floats = 33 KB.
__device__ float g_inter[TOPK * INTER];

__device__ __forceinline__ float dot4(float4 a, float4 b) {
    return a.x * b.x + a.y * b.y + a.z * b.z + a.w * b.w;
}

// ---------------------------------------------------------------------------
// Kernel 1: inter[k][i] = silu(gate_i . x) * (up_i . x)
// 256-thread block per (i-pair, expert). 10 float4 loads front-batched per
// thread -> ~6.4 TB/s measured.
// ---------------------------------------------------------------------------
__global__ void __launch_bounds__(256, 8)
gate_up_silu_kernel(const float* __restrict__ x,
                    const int* __restrict__ topk_idx,
                    const float* __restrict__ gu_all)
{
    const int i0 = blockIdx.x * 2;     // 0..1406 step 2
    const int k  = blockIdx.y;         // 0..5
    const int t  = threadIdx.x;

    const int e = topk_idx[k];
    const size_t base = ((size_t)e * (2 * INTER) + i0) * HIDDEN;

    const float4* __restrict__ xg  = (const float4*)x;
    const float4* __restrict__ g0p = (const float4*)(gu_all + base);
    const float4* __restrict__ g1p = (const float4*)(gu_all + base + HIDDEN);
    const float4* __restrict__ u0p = (const float4*)(gu_all + base + (size_t)INTER * HIDDEN);
    const float4* __restrict__ u1p = (const float4*)(gu_all + base + (size_t)INTER * HIDDEN + HIDDEN);

    float s0 = 0.f, s1 = 0.f, s2 = 0.f, s3 = 0.f;
    #pragma unroll
    for (int jj = 0; jj < 2; ++jj) {
        const int j = t + jj * 256;    // HIDDEN/4 = 512
        float4 xv = xg[j];
        float4 a  = g0p[j];
        float4 b  = g1p[j];
        float4 c  = u0p[j];
        float4 d  = u1p[j];
        s0 += dot4(xv, a);
        s1 += dot4(xv, b);
        s2 += dot4(xv, c);
        s3 += dot4(xv, d);
    }

    #pragma unroll
    for (int off = 16; off > 0; off >>= 1) {
        s0 += __shfl_down_sync(0xffffffff, s0, off);
        s1 += __shfl_down_sync(0xffffffff, s1, off);
        s2 += __shfl_down_sync(0xffffffff, s2, off);
        s3 += __shfl_down_sync(0xffffffff, s3, off);
    }

    __shared__ float sm[8][4];
    const int wid = t >> 5, lid = t & 31;
    if (lid == 0) { sm[wid][0] = s0; sm[wid][1] = s1; sm[wid][2] = s2; sm[wid][3] = s3; }
    __syncthreads();

    if (t == 0) {
        float G0 = 0.f, G1 = 0.f, U0 = 0.f, U1 = 0.f;
        #pragma unroll
        for (int w = 0; w < 8; ++w) {
            G0 += sm[w][0]; G1 += sm[w][1]; U0 += sm[w][2]; U1 += sm[w][3];
        }
        g_inter[k * INTER + i0]     = (G0 / (1.0f + expf(-G0))) * U0;
        g_inter[k * INTER + i0 + 1] = (G1 / (1.0f + expf(-G1))) * U1;
    }
}

// ---------------------------------------------------------------------------
// Kernel 2: out[h] = sum_k w[k] * dot(down[e_k][h][:], inter[k][:])
// One 192-thread block per h-PAIR; warp w handles expert k=w independently
// for BOTH rows h0, h0+1:
//   22 front-batched DRAM float4 + 11 L2-hot inter float4 per lane.
// Per-warp setup/reduce overhead amortized over 2 rows; warps decoupled
// until one tiny smem combine.
// ---------------------------------------------------------------------------
__global__ void __launch_bounds__(192)
down_kernel(const int* __restrict__ topk_idx,
            const float* __restrict__ topk_w,
            const float* __restrict__ down_all,
            float* __restrict__ out)
{
    const int h0  = blockIdx.x * 2;    // 0..2046 step 2
    const int k   = threadIdx.x >> 5;  // warp id = expert slot 0..5
    const int lid = threadIdx.x & 31;

    const int e = topk_idx[k];
    const float* rowbase = down_all + ((size_t)e * HIDDEN + h0) * INTER;
    const float4* __restrict__ dr0 = (const float4*)rowbase;
    const float4* __restrict__ dr1 = (const float4*)(rowbase + INTER);
    const float4* __restrict__ iv  = (const float4*)(g_inter + k * INTER);

    float a0 = 0.f, a1 = 0.f;
    // 352 float4 per row / 32 lanes = 11 iterations, fully unrolled.
    #pragma unroll
    for (int jj = 0; jj < 11; ++jj) {
        const int j = lid + jj * 32;
        float4 d0 = dr0[j];
        float4 d1 = dr1[j];
        float4 vv = iv[j];
        a0 += dot4(d0, vv);
        a1 += dot4(d1, vv);
    }

    // warp reduce both rows
    #pragma unroll
    for (int off = 16; off > 0; off >>= 1) {
        a0 += __shfl_down_sync(0xffffffff, a0, off);
        a1 += __shfl_down_sync(0xffffffff, a1, off);
    }

    __shared__ float sk[2][TOPK];
    if (lid == 0) { sk[0][k] = a0; sk[1][k] = a1; }
    __syncthreads();

    if (threadIdx.x < 2) {
        const int hh = threadIdx.x;
        float total = 0.f;
        #pragma unroll
        for (int kk = 0; kk < TOPK; ++kk)
            total += topk_w[kk] * sk[hh][kk];
        out[h0 + hh] = total;
    }
}

// ---------------------------------------------------------------------------
extern "C" void kernel_launch(void* const* d_in, const int* in_sizes, int n_in,
                              void* d_out, int out_size)
{
    const float* x        = (const float*)d_in[0];      // [1,2048,1,1]
    const int*   topk_idx = (const int*)d_in[1];        // [6] int32
    const float* topk_w   = (const float*)d_in[2];      // [6]
    const float* gu_all   = (const float*)d_in[3];      // [60, 2816, 2048]
    const float* down_all = (const float*)d_in[4];      // [60, 2048, 1408]
    float*       out      = (float*)d_out;              // [2048]

    dim3 grid1(INTER / 2, TOPK);
    gate_up_silu_kernel<<<grid1, 256>>>(x, topk_idx, gu_all);

    down_kernel<<<HIDDEN / 2, 192>>>(topk_idx, topk_w, down_all, out);
}

// round 8
// speedup vs baseline: 1.0073x; 1.0073x over previous
#include <cuda_runtime.h>

#define HIDDEN 2048
#define INTER  1408
#define TOPK   6
#define CHUNK  4   // h rows per block in down_kernel

// Scratch for intermediate activations (silu(gate)*up): 6*1408 floats = 33 KB.
__device__ float g_inter[TOPK * INTER];

__device__ __forceinline__ float dot4(float4 a, float4 b) {
    return a.x * b.x + a.y * b.y + a.z * b.z + a.w * b.w;
}

// ---------------------------------------------------------------------------
// Kernel 1: inter[k][i] = silu(gate_i . x) * (up_i . x)
// 256-thread block per (i-pair, expert). 10 float4 loads front-batched per
// thread -> ~6.4 TB/s measured.
// ---------------------------------------------------------------------------
__global__ void __launch_bounds__(256, 8)
gate_up_silu_kernel(const float* __restrict__ x,
                    const int* __restrict__ topk_idx,
                    const float* __restrict__ gu_all)
{
    const int i0 = blockIdx.x * 2;     // 0..1406 step 2
    const int k  = blockIdx.y;         // 0..5
    const int t  = threadIdx.x;

    const int e = topk_idx[k];
    const size_t base = ((size_t)e * (2 * INTER) + i0) * HIDDEN;

    const float4* __restrict__ xg  = (const float4*)x;
    const float4* __restrict__ g0p = (const float4*)(gu_all + base);
    const float4* __restrict__ g1p = (const float4*)(gu_all + base + HIDDEN);
    const float4* __restrict__ u0p = (const float4*)(gu_all + base + (size_t)INTER * HIDDEN);
    const float4* __restrict__ u1p = (const float4*)(gu_all + base + (size_t)INTER * HIDDEN + HIDDEN);

    float s0 = 0.f, s1 = 0.f, s2 = 0.f, s3 = 0.f;
    #pragma unroll
    for (int jj = 0; jj < 2; ++jj) {
        const int j = t + jj * 256;    // HIDDEN/4 = 512
        float4 xv = xg[j];
        float4 a  = g0p[j];
        float4 b  = g1p[j];
        float4 c  = u0p[j];
        float4 d  = u1p[j];
        s0 += dot4(xv, a);
        s1 += dot4(xv, b);
        s2 += dot4(xv, c);
        s3 += dot4(xv, d);
    }

    #pragma unroll
    for (int off = 16; off > 0; off >>= 1) {
        s0 += __shfl_down_sync(0xffffffff, s0, off);
        s1 += __shfl_down_sync(0xffffffff, s1, off);
        s2 += __shfl_down_sync(0xffffffff, s2, off);
        s3 += __shfl_down_sync(0xffffffff, s3, off);
    }

    __shared__ float sm[8][4];
    const int wid = t >> 5, lid = t & 31;
    if (lid == 0) { sm[wid][0] = s0; sm[wid][1] = s1; sm[wid][2] = s2; sm[wid][3] = s3; }
    __syncthreads();

    if (t == 0) {
        float G0 = 0.f, G1 = 0.f, U0 = 0.f, U1 = 0.f;
        #pragma unroll
        for (int w = 0; w < 8; ++w) {
            G0 += sm[w][0]; G1 += sm[w][1]; U0 += sm[w][2]; U1 += sm[w][3];
        }
        g_inter[k * INTER + i0]     = (G0 / (1.0f + expf(-G0))) * U0;
        g_inter[k * INTER + i0 + 1] = (G1 / (1.0f + expf(-G1))) * U1;
    }
}

// ---------------------------------------------------------------------------
// Kernel 2: out[h] = sum_k w[k] * dot(down[e_k][h][:], inter[k][:])
// 192-thread block per CHUNK of h rows. Warp w = expert slot w; loads its
// inter slice ONCE into 11 float4 registers, then streams CHUNK weight rows
// (pure DRAM traffic in the inner loop, zero repeated inter reads).
// ---------------------------------------------------------------------------
__global__ void __launch_bounds__(192)
down_kernel(const int* __restrict__ topk_idx,
            const float* __restrict__ topk_w,
            const float* __restrict__ down_all,
            float* __restrict__ out)
{
    const int h0  = blockIdx.x * CHUNK;
    const int k   = threadIdx.x >> 5;  // warp id = expert slot 0..5
    const int lid = threadIdx.x & 31;

    const int e = topk_idx[k];

    // Register-resident inter slice: 352 float4 / 32 lanes = 11 per lane.
    float4 vv[11];
    {
        const float4* __restrict__ iv = (const float4*)(g_inter + k * INTER);
        #pragma unroll
        for (int jj = 0; jj < 11; ++jj)
            vv[jj] = iv[lid + jj * 32];
    }

    const float* rowbase = down_all + ((size_t)e * HIDDEN + h0) * INTER;

    __shared__ float sk[CHUNK][TOPK];

    // Process CHUNK rows as pairs (2 accumulators in flight per pass).
    #pragma unroll
    for (int p = 0; p < CHUNK / 2; ++p) {
        const float4* __restrict__ r0 = (const float4*)(rowbase + (2 * p) * INTER);
        const float4* __restrict__ r1 = (const float4*)(rowbase + (2 * p + 1) * INTER);

        float a0 = 0.f, a1 = 0.f;
        #pragma unroll
        for (int jj = 0; jj < 11; ++jj) {
            const int j = lid + jj * 32;
            a0 += dot4(r0[j], vv[jj]);
            a1 += dot4(r1[j], vv[jj]);
        }

        #pragma unroll
        for (int off = 16; off > 0; off >>= 1) {
            a0 += __shfl_down_sync(0xffffffff, a0, off);
            a1 += __shfl_down_sync(0xffffffff, a1, off);
        }
        if (lid == 0) { sk[2 * p][k] = a0; sk[2 * p + 1][k] = a1; }
    }
    __syncthreads();

    if (threadIdx.x < CHUNK) {
        const int hh = threadIdx.x;
        float total = 0.f;
        #pragma unroll
        for (int kk = 0; kk < TOPK; ++kk)
            total += topk_w[kk] * sk[hh][kk];
        out[h0 + hh] = total;
    }
}

// ---------------------------------------------------------------------------
extern "C" void kernel_launch(void* const* d_in, const int* in_sizes, int n_in,
                              void* d_out, int out_size)
{
    const float* x        = (const float*)d_in[0];      // [1,2048,1,1]
    const int*   topk_idx = (const int*)d_in[1];        // [6] int32
    const float* topk_w   = (const float*)d_in[2];      // [6]
    const float* gu_all   = (const float*)d_in[3];      // [60, 2816, 2048]
    const float* down_all = (const float*)d_in[4];      // [60, 2048, 1408]
    float*       out      = (float*)d_out;              // [2048]

    dim3 grid1(INTER / 2, TOPK);
    gate_up_silu_kernel<<<grid1, 256>>>(x, topk_idx, gu_all);

    down_kernel<<<HIDDEN / CHUNK, 192>>>(topk_idx, topk_w, down_all, out);
}